// round 2
// baseline (speedup 1.0000x reference)
#include <cuda_runtime.h>
#include <cuda_bf16.h>
#include <cstdint>

// ---------------- Problem constants ----------------
#define QLEN   2048
#define DMODEL 4096
#define NHEAD  32
#define NKVH   8
#define HEADD  128
#define NSINK  4
#define NWIN   2048
#define NSNW   (NSINK + NWIN)          // 2052
#define KTOT   (NSNW + QLEN)           // 4100
#define GRP    (NHEAD / NKVH)          // 4
#define KVDIM  (NKVH * HEADD)          // 1024

#define NEG_BIG (-3.4028234663852886e38f)   // finfo(float32).min
#define LOG10000_OVER_64 0.14391156831212787f
#define ATTN_SCALE 0.08838834764831845f     // 1/sqrt(128)

// ---------------- Scratch (device globals; no runtime alloc) ----------------
__device__ float g_q[QLEN * DMODEL];        // q projection, then RoPE'd in place
__device__ float g_kproj[QLEN * KVDIM];
__device__ float g_vproj[QLEN * KVDIM];
__device__ float g_K[NKVH * KTOT * HEADD];  // concatenated, RoPE'd K cache
__device__ float g_V[NKVH * KTOT * HEADD];
__device__ float g_attn[QLEN * DMODEL];     // attention output (pre-Wo)
__device__ float g_bias[NSNW];              // cache bias (mask * NEG)
__device__ int   g_maxpos;

__device__ __forceinline__ float neg_inf() { return __int_as_float(0xff800000u); }

// ---------------- max position + bias precompute ----------------
__global__ void maxpos_kernel(const int* __restrict__ sink_pos,
                              const int* __restrict__ key_pos) {
    __shared__ int sm[256];
    int tid = threadIdx.x;
    int v = -2147483647;
    for (int i = tid; i < NWIN; i += 256) v = max(v, key_pos[i]);
    for (int i = tid; i < NSINK; i += 256) v = max(v, sink_pos[i]);
    sm[tid] = v;
    __syncthreads();
    for (int s = 128; s > 0; s >>= 1) {
        if (tid < s) sm[tid] = max(sm[tid], sm[tid + s]);
        __syncthreads();
    }
    if (tid == 0) g_maxpos = sm[0] + 1;
}

__global__ void bias_kernel(const float* __restrict__ sink_mask,
                            const float* __restrict__ key_mask) {
    int i = blockIdx.x * blockDim.x + threadIdx.x;
    if (i >= NSNW) return;
    float m = (i < NSINK) ? sink_mask[i] : key_mask[i - NSINK];
    g_bias[i] = m * NEG_BIG;
}

// ---------------- classic SGEMM: C[M,N] = A[M,K] @ B[K,N], all row-major ----------------
// 128x128 block tile, K-step 8, 256 threads, 8x8 per-thread micro tile.
// Requires M%128==0, N%128==0, K%8==0 (true for all calls here).
__global__ void __launch_bounds__(256) sgemm128(
    const float* __restrict__ A, const float* __restrict__ B,
    float* __restrict__ C, int M, int N, int K) {
    __shared__ float As[8][128];
    __shared__ float Bs[8][128];

    const int tid  = threadIdx.x;
    const int cRow = blockIdx.y * 128;
    const int cCol = blockIdx.x * 128;

    const int aRow = tid >> 1;               // 0..127
    const int aCol = (tid & 1) * 4;          // 0 or 4
    const int bRow = tid >> 5;               // 0..7
    const int bCol = (tid & 31) * 4;         // 0..124
    const int tRow = (tid >> 4) * 8;         // 0..120
    const int tCol = (tid & 15) * 8;

    float acc[8][8];
#pragma unroll
    for (int i = 0; i < 8; i++)
#pragma unroll
        for (int j = 0; j < 8; j++) acc[i][j] = 0.f;

    for (int k0 = 0; k0 < K; k0 += 8) {
        float4 a = *(const float4*)(A + (size_t)(cRow + aRow) * K + k0 + aCol);
        As[aCol + 0][aRow] = a.x;
        As[aCol + 1][aRow] = a.y;
        As[aCol + 2][aRow] = a.z;
        As[aCol + 3][aRow] = a.w;
        *(float4*)(&Bs[bRow][bCol]) =
            *(const float4*)(B + (size_t)(k0 + bRow) * N + cCol + bCol);
        __syncthreads();

#pragma unroll
        for (int kk = 0; kk < 8; kk++) {
            float4 m0 = *(const float4*)(&As[kk][tRow]);
            float4 m1 = *(const float4*)(&As[kk][tRow + 4]);
            float4 n0 = *(const float4*)(&Bs[kk][tCol]);
            float4 n1 = *(const float4*)(&Bs[kk][tCol + 4]);
            float rm[8] = {m0.x, m0.y, m0.z, m0.w, m1.x, m1.y, m1.z, m1.w};
            float rn[8] = {n0.x, n0.y, n0.z, n0.w, n1.x, n1.y, n1.z, n1.w};
#pragma unroll
            for (int i = 0; i < 8; i++)
#pragma unroll
                for (int j = 0; j < 8; j++) acc[i][j] = fmaf(rm[i], rn[j], acc[i][j]);
        }
        __syncthreads();
    }

#pragma unroll
    for (int i = 0; i < 8; i++) {
        float4 v0 = {acc[i][0], acc[i][1], acc[i][2], acc[i][3]};
        float4 v1 = {acc[i][4], acc[i][5], acc[i][6], acc[i][7]};
        float* cp = C + (size_t)(cRow + tRow + i) * N + cCol + tCol;
        *(float4*)cp       = v0;
        *(float4*)(cp + 4) = v1;
    }
}

// ---------------- RoPE on q (in place). One thread per (token, head, pair) ----------------
__global__ void rope_q_kernel() {
    int idx = blockIdx.x * blockDim.x + threadIdx.x;
    if (idx >= QLEN * NHEAD * 64) return;
    int i  = idx & 63;
    int hq = idx >> 6;
    int h  = hq & (NHEAD - 1);
    int t  = hq >> 5;                     // NHEAD == 32
    float* p = g_q + (size_t)t * DMODEL + h * HEADD;
    float pos = (float)(g_maxpos + t);
    float freq = expf(-(float)i * LOG10000_OVER_64);
    float ang = pos * freq;
    float c, s;
    sincosf(ang, &s, &c);
    float x1 = p[i], x2 = p[i + 64];
    p[i]      = x1 * c - x2 * s;
    p[i + 64] = x2 * c + x1 * s;
}

// ---------------- Build concatenated K (RoPE'd) and V caches ----------------
__global__ void build_cache_kernel(const float* __restrict__ sink_k,
                                   const float* __restrict__ sink_v,
                                   const float* __restrict__ win_k,
                                   const float* __restrict__ win_v,
                                   const int* __restrict__ sink_pos,
                                   const int* __restrict__ key_pos) {
    int idx = blockIdx.x * blockDim.x + threadIdx.x;
    if (idx >= NKVH * KTOT * 64) return;
    int i   = idx & 63;
    int rj  = idx >> 6;
    int j   = rj % KTOT;
    int kvh = rj / KTOT;

    const float* kp;
    const float* vp;
    int pos;
    if (j < NSINK) {
        kp = sink_k + (size_t)(kvh * NSINK + j) * HEADD;
        vp = sink_v + (size_t)(kvh * NSINK + j) * HEADD;
        pos = sink_pos[j];
    } else if (j < NSNW) {
        int w = j - NSINK;
        kp = win_k + (size_t)(kvh * NWIN + w) * HEADD;
        vp = win_v + (size_t)(kvh * NWIN + w) * HEADD;
        pos = key_pos[w];
    } else {
        int t = j - NSNW;
        kp = g_kproj + (size_t)t * KVDIM + kvh * HEADD;
        vp = g_vproj + (size_t)t * KVDIM + kvh * HEADD;
        pos = g_maxpos + t;
    }

    float freq = expf(-(float)i * LOG10000_OVER_64);
    float ang = (float)pos * freq;
    float c, s;
    sincosf(ang, &s, &c);
    float x1 = kp[i], x2 = kp[i + 64];

    size_t out = ((size_t)kvh * KTOT + j) * HEADD;
    g_K[out + i]      = x1 * c - x2 * s;
    g_K[out + i + 64] = x2 * c + x1 * s;
    g_V[out + i]      = vp[i];
    g_V[out + i + 64] = vp[i + 64];
}

// ---------------- Attention: warp per query row, online softmax, 32-key smem chunks ----------------
__global__ void __launch_bounds__(256) attn_kernel() {
    __shared__ float4 Ks[32][32];   // 32 keys x 128 dims
    __shared__ float4 Vs[32][32];

    const int h    = blockIdx.x;
    const int kvh  = h >> 2;                     // GRP = 4
    const int warp = threadIdx.x >> 5;
    const int lane = threadIdx.x & 31;
    const int qt   = blockIdx.y * 8 + warp;      // query token

    const float* qp = g_q + (size_t)qt * DMODEL + h * HEADD;
    float4 qf = *(const float4*)(qp + lane * 4);

    float4 o = {0.f, 0.f, 0.f, 0.f};
    float m = neg_inf(), l = 0.f;

    const int kmaxBlock = NSNW + (blockIdx.y * 8 + 7) + 1; // keys the block needs
    const float* Kbase = g_K + (size_t)kvh * KTOT * HEADD;
    const float* Vbase = g_V + (size_t)kvh * KTOT * HEADD;

    for (int c0 = 0; c0 < kmaxBlock; c0 += 32) {
        // cooperative chunk load
        for (int ii = threadIdx.x; ii < 32 * 32; ii += 256) {
            int r = ii >> 5, c = ii & 31;
            int j = c0 + r;
            if (j < KTOT) {
                Ks[r][c] = *(const float4*)(Kbase + (size_t)j * HEADD + c * 4);
                Vs[r][c] = *(const float4*)(Vbase + (size_t)j * HEADD + c * 4);
            } else {
                Ks[r][c] = make_float4(0.f, 0.f, 0.f, 0.f);
                Vs[r][c] = make_float4(0.f, 0.f, 0.f, 0.f);
            }
        }
        __syncthreads();

        float sc[32];
        float cmax = neg_inf();
#pragma unroll
        for (int k = 0; k < 32; k++) {
            int j = c0 + k;
            float4 kf = Ks[k][lane];
            float p = qf.x * kf.x + qf.y * kf.y + qf.z * kf.z + qf.w * kf.w;
            p += __shfl_xor_sync(0xffffffffu, p, 16);
            p += __shfl_xor_sync(0xffffffffu, p, 8);
            p += __shfl_xor_sync(0xffffffffu, p, 4);
            p += __shfl_xor_sync(0xffffffffu, p, 2);
            p += __shfl_xor_sync(0xffffffffu, p, 1);
            float b;
            if (j < NSNW) b = g_bias[j];
            else          b = (j - NSNW <= qt) ? 0.f : neg_inf();
            float sval = p * ATTN_SCALE + b;
            sc[k] = sval;
            cmax = fmaxf(cmax, sval);
        }

        float mn = fmaxf(m, cmax);
        if (mn != neg_inf()) {
            float r = (m == neg_inf()) ? 0.f : __expf(m - mn);
            l *= r;
            o.x *= r; o.y *= r; o.z *= r; o.w *= r;
#pragma unroll
            for (int k = 0; k < 32; k++) {
                float p = __expf(sc[k] - mn);   // -inf -> 0
                float4 vf = Vs[k][lane];
                l += p;
                o.x = fmaf(p, vf.x, o.x);
                o.y = fmaf(p, vf.y, o.y);
                o.z = fmaf(p, vf.z, o.z);
                o.w = fmaf(p, vf.w, o.w);
            }
            m = mn;
        }
        __syncthreads();
    }

    float inv = 1.f / l;
    o.x *= inv; o.y *= inv; o.z *= inv; o.w *= inv;
    *(float4*)(g_attn + (size_t)qt * DMODEL + h * HEADD + lane * 4) = o;
}

// ---------------- launch ----------------
extern "C" void kernel_launch(void* const* d_in, const int* in_sizes, int n_in,
                              void* d_out, int out_size) {
    const float* hidden    = (const float*)d_in[0];
    const float* sink_k    = (const float*)d_in[1];
    const float* sink_v    = (const float*)d_in[2];
    const float* win_k     = (const float*)d_in[3];
    const float* win_v     = (const float*)d_in[4];
    const int*   sink_pos  = (const int*)d_in[5];
    const int*   key_pos   = (const int*)d_in[6];
    const float* sink_mask = (const float*)d_in[7];
    const float* key_mask  = (const float*)d_in[8];
    const float* Wq        = (const float*)d_in[9];
    const float* Wk        = (const float*)d_in[10];
    const float* Wv        = (const float*)d_in[11];
    const float* Wo        = (const float*)d_in[12];
    float*       out       = (float*)d_out;

    float *pq, *pk, *pv, *pattn;
    cudaGetSymbolAddress((void**)&pq, g_q);
    cudaGetSymbolAddress((void**)&pk, g_kproj);
    cudaGetSymbolAddress((void**)&pv, g_vproj);
    cudaGetSymbolAddress((void**)&pattn, g_attn);

    maxpos_kernel<<<1, 256>>>(sink_pos, key_pos);
    bias_kernel<<<(NSNW + 255) / 256, 256>>>(sink_mask, key_mask);

    // projections
    sgemm128<<<dim3(DMODEL / 128, QLEN / 128), 256>>>(hidden, Wq, pq, QLEN, DMODEL, DMODEL);
    sgemm128<<<dim3(KVDIM / 128, QLEN / 128), 256>>>(hidden, Wk, pk, QLEN, KVDIM, DMODEL);
    sgemm128<<<dim3(KVDIM / 128, QLEN / 128), 256>>>(hidden, Wv, pv, QLEN, KVDIM, DMODEL);

    // RoPE + cache assembly
    rope_q_kernel<<<(QLEN * NHEAD * 64 + 255) / 256, 256>>>();
    build_cache_kernel<<<(NKVH * KTOT * 64 + 255) / 256, 256>>>(
        sink_k, sink_v, win_k, win_v, sink_pos, key_pos);

    // attention
    attn_kernel<<<dim3(NHEAD, QLEN / 8), 256>>>();

    // output projection
    sgemm128<<<dim3(DMODEL / 128, QLEN / 128), 256>>>(pattn, Wo, out, QLEN, DMODEL, DMODEL);
}

// round 3
// speedup vs baseline: 2.2601x; 2.2601x over previous
#include <cuda_runtime.h>
#include <cuda_bf16.h>
#include <cstdint>

// ---------------- Problem constants ----------------
#define QLEN   2048
#define DMODEL 4096
#define NHEAD  32
#define NKVH   8
#define HEADD  128
#define NSINK  4
#define NWIN   2048
#define NSNW   (NSINK + NWIN)          // 2052
#define KTOT   (NSNW + QLEN)           // 4100
#define GRP    (NHEAD / NKVH)          // 4
#define KVDIM  (NKVH * HEADD)          // 1024

#define NEG_BIG (-3.4028234663852886e38f)   // finfo(float32).min
#define LOG10000_OVER_64 0.14391156831212787f
#define ATTN_SCALE 0.08838834764831845f     // 1/sqrt(128)

// ---------------- Scratch (device globals; no runtime alloc) ----------------
__device__ float g_q[QLEN * DMODEL];        // q projection, then RoPE'd in place
__device__ float g_kproj[QLEN * KVDIM];
__device__ float g_vproj[QLEN * KVDIM];
__device__ float g_K[NKVH * KTOT * HEADD];  // concatenated, RoPE'd K cache
__device__ float g_V[NKVH * KTOT * HEADD];
__device__ float g_attn[QLEN * DMODEL];     // attention output (pre-Wo)
__device__ float g_bias[NSNW];              // cache bias (mask * NEG)
__device__ int   g_maxpos;

__device__ __forceinline__ float neg_inf() { return __int_as_float(0xff800000u); }

__device__ __forceinline__ uint32_t f2tf32(float x) {
    uint32_t u;
    asm("cvt.rna.tf32.f32 %0, %1;" : "=r"(u) : "f"(x));
    return u;
}

__device__ __forceinline__ void mma_tf32(float d[4],
                                         uint32_t a0, uint32_t a1, uint32_t a2, uint32_t a3,
                                         uint32_t b0, uint32_t b1) {
    asm volatile(
        "mma.sync.aligned.m16n8k8.row.col.f32.tf32.tf32.f32 "
        "{%0,%1,%2,%3}, {%4,%5,%6,%7}, {%8,%9}, {%0,%1,%2,%3};\n"
        : "+f"(d[0]), "+f"(d[1]), "+f"(d[2]), "+f"(d[3])
        : "r"(a0), "r"(a1), "r"(a2), "r"(a3), "r"(b0), "r"(b1));
}

// ---------------- max position + bias precompute ----------------
__global__ void maxpos_kernel(const int* __restrict__ sink_pos,
                              const int* __restrict__ key_pos) {
    __shared__ int sm[256];
    int tid = threadIdx.x;
    int v = -2147483647;
    for (int i = tid; i < NWIN; i += 256) v = max(v, key_pos[i]);
    for (int i = tid; i < NSINK; i += 256) v = max(v, sink_pos[i]);
    sm[tid] = v;
    __syncthreads();
    for (int s = 128; s > 0; s >>= 1) {
        if (tid < s) sm[tid] = max(sm[tid], sm[tid + s]);
        __syncthreads();
    }
    if (tid == 0) g_maxpos = sm[0] + 1;
}

__global__ void bias_kernel(const float* __restrict__ sink_mask,
                            const float* __restrict__ key_mask) {
    int i = blockIdx.x * blockDim.x + threadIdx.x;
    if (i >= NSNW) return;
    float m = (i < NSINK) ? sink_mask[i] : key_mask[i - NSINK];
    g_bias[i] = m * NEG_BIG;
}

// ---------------- TF32 tensor-core GEMM: C[M,N] = A[M,K] @ B[K,N], row-major ----------------
// 128x128x32 block tile, 256 threads (8 warps, 4x2), warp tile 32x64,
// m16n8k8 tf32 mma. Smem stored k-major with stride 136 (conflict-free frags).
#define GSTR 136
__global__ void __launch_bounds__(256) gemm_tf32(
    const float* __restrict__ A, const float* __restrict__ B,
    float* __restrict__ C, int M, int N, int K) {
    __shared__ uint32_t As[32][GSTR];   // As[k][m]
    __shared__ uint32_t Bs[32][GSTR];   // Bs[k][n]

    const int tid  = threadIdx.x;
    const int lane = tid & 31;
    const int warp = tid >> 5;
    const int wm   = (warp >> 1) * 32;
    const int wn   = (warp & 1) * 64;
    const int cRow = blockIdx.y * 128;
    const int cCol = blockIdx.x * 128;
    const int r0   = lane >> 2;       // group id 0..7
    const int cq   = lane & 3;        // thread-in-group 0..3

    float acc[2][8][4];
#pragma unroll
    for (int mt = 0; mt < 2; mt++)
#pragma unroll
        for (int nt = 0; nt < 8; nt++)
#pragma unroll
            for (int f = 0; f < 4; f++) acc[mt][nt][f] = 0.f;

    for (int k0 = 0; k0 < K; k0 += 32) {
#pragma unroll
        for (int i = 0; i < 4; i++) {          // A tile: 128 x 32
            int e = (i * 256 + tid) * 4;
            int r = e >> 5, c = e & 31;
            float4 v = *(const float4*)(A + (size_t)(cRow + r) * K + k0 + c);
            As[c + 0][r] = f2tf32(v.x);
            As[c + 1][r] = f2tf32(v.y);
            As[c + 2][r] = f2tf32(v.z);
            As[c + 3][r] = f2tf32(v.w);
        }
#pragma unroll
        for (int i = 0; i < 4; i++) {          // B tile: 32 x 128
            int e = (i * 256 + tid) * 4;
            int r = e >> 7, c = e & 127;
            float4 v = *(const float4*)(B + (size_t)(k0 + r) * N + cCol + c);
            uint4 u = {f2tf32(v.x), f2tf32(v.y), f2tf32(v.z), f2tf32(v.w)};
            *(uint4*)&Bs[r][c] = u;
        }
        __syncthreads();

#pragma unroll
        for (int kk = 0; kk < 4; kk++) {
            const int kb = kk * 8;
            uint32_t af[2][4];
#pragma unroll
            for (int mt = 0; mt < 2; mt++) {
                int mr = wm + mt * 16 + r0;
                af[mt][0] = As[kb + cq][mr];
                af[mt][1] = As[kb + cq][mr + 8];
                af[mt][2] = As[kb + 4 + cq][mr];
                af[mt][3] = As[kb + 4 + cq][mr + 8];
            }
#pragma unroll
            for (int nt = 0; nt < 8; nt++) {
                int nc = wn + nt * 8 + r0;
                uint32_t b0 = Bs[kb + cq][nc];
                uint32_t b1 = Bs[kb + 4 + cq][nc];
                mma_tf32(acc[0][nt], af[0][0], af[0][1], af[0][2], af[0][3], b0, b1);
                mma_tf32(acc[1][nt], af[1][0], af[1][1], af[1][2], af[1][3], b0, b1);
            }
        }
        __syncthreads();
    }

#pragma unroll
    for (int mt = 0; mt < 2; mt++)
#pragma unroll
        for (int nt = 0; nt < 8; nt++) {
            int r = cRow + wm + mt * 16 + r0;
            int c = cCol + wn + nt * 8 + cq * 2;
            float2 v0 = {acc[mt][nt][0], acc[mt][nt][1]};
            float2 v1 = {acc[mt][nt][2], acc[mt][nt][3]};
            *(float2*)(C + (size_t)r * N + c)       = v0;
            *(float2*)(C + (size_t)(r + 8) * N + c) = v1;
        }
}

// ---------------- RoPE on q (in place). One thread per (token, head, pair) ----------------
__global__ void rope_q_kernel() {
    int idx = blockIdx.x * blockDim.x + threadIdx.x;
    if (idx >= QLEN * NHEAD * 64) return;
    int i  = idx & 63;
    int hq = idx >> 6;
    int h  = hq & (NHEAD - 1);
    int t  = hq >> 5;                     // NHEAD == 32
    float* p = g_q + (size_t)t * DMODEL + h * HEADD;
    float pos = (float)(g_maxpos + t);
    float freq = expf(-(float)i * LOG10000_OVER_64);
    float ang = pos * freq;
    float c, s;
    sincosf(ang, &s, &c);
    float x1 = p[i], x2 = p[i + 64];
    p[i]      = x1 * c - x2 * s;
    p[i + 64] = x2 * c + x1 * s;
}

// ---------------- Build concatenated K (RoPE'd) and V caches ----------------
__global__ void build_cache_kernel(const float* __restrict__ sink_k,
                                   const float* __restrict__ sink_v,
                                   const float* __restrict__ win_k,
                                   const float* __restrict__ win_v,
                                   const int* __restrict__ sink_pos,
                                   const int* __restrict__ key_pos) {
    int idx = blockIdx.x * blockDim.x + threadIdx.x;
    if (idx >= NKVH * KTOT * 64) return;
    int i   = idx & 63;
    int rj  = idx >> 6;
    int j   = rj % KTOT;
    int kvh = rj / KTOT;

    const float* kp;
    const float* vp;
    int pos;
    if (j < NSINK) {
        kp = sink_k + (size_t)(kvh * NSINK + j) * HEADD;
        vp = sink_v + (size_t)(kvh * NSINK + j) * HEADD;
        pos = sink_pos[j];
    } else if (j < NSNW) {
        int w = j - NSINK;
        kp = win_k + (size_t)(kvh * NWIN + w) * HEADD;
        vp = win_v + (size_t)(kvh * NWIN + w) * HEADD;
        pos = key_pos[w];
    } else {
        int t = j - NSNW;
        kp = g_kproj + (size_t)t * KVDIM + kvh * HEADD;
        vp = g_vproj + (size_t)t * KVDIM + kvh * HEADD;
        pos = g_maxpos + t;
    }

    float freq = expf(-(float)i * LOG10000_OVER_64);
    float ang = (float)pos * freq;
    float c, s;
    sincosf(ang, &s, &c);
    float x1 = kp[i], x2 = kp[i + 64];

    size_t out = ((size_t)kvh * KTOT + j) * HEADD;
    g_K[out + i]      = x1 * c - x2 * s;
    g_K[out + i + 64] = x2 * c + x1 * s;
    g_V[out + i]      = vp[i];
    g_V[out + i + 64] = vp[i + 64];
}

// ---------------- Flash attention with tf32 mma ----------------
// Block: (head, 64-query tile). 4 warps, each owns 16 q rows.
// Smem (dynamic, uint32 words):
//   Qs[128][72]  (d-major, tf32)       36864 B
//   Ks[128][72]  (d-major, tf32)       36864 B
//   Vs[64][136]  (key-major, tf32)     34816 B
//   Ps[64][72]   (key-major, tf32)     18432 B
//   biasS[64]    (float)                 256 B
#define QS_STR 72
#define VS_STR 136
#define ATTN_SMEM_WORDS (128*QS_STR + 128*QS_STR + 64*VS_STR + 64*QS_STR + 64)
#define ATTN_SMEM_BYTES (ATTN_SMEM_WORDS * 4)

__global__ void __launch_bounds__(128) attn_mma_kernel() {
    extern __shared__ uint32_t smw[];
    uint32_t* Qs = smw;
    uint32_t* Ks = Qs + 128 * QS_STR;
    uint32_t* Vs = Ks + 128 * QS_STR;
    uint32_t* Ps = Vs + 64 * VS_STR;
    float* biasS = (float*)(Ps + 64 * QS_STR);

    const int h    = blockIdx.x;
    const int kvh  = h >> 2;                 // GRP = 4
    const int qt0  = blockIdx.y * 64;
    const int tid  = threadIdx.x;
    const int lane = tid & 31;
    const int warp = tid >> 5;
    const int qw   = warp * 16;              // warp's q offset within tile
    const int r0   = lane >> 2;              // 0..7
    const int cq   = lane & 3;               // 0..3

    // ---- load Q tile (64 q x 128 d) into Qs[d][q], tf32 ----
    const float* qg = g_q + (size_t)qt0 * DMODEL + h * HEADD;
    for (int i = tid; i < 64 * 32; i += 128) {
        int q = i >> 5, c4 = (i & 31) * 4;
        float4 v = *(const float4*)(qg + (size_t)q * DMODEL + c4);
        Qs[(c4 + 0) * QS_STR + q] = f2tf32(v.x);
        Qs[(c4 + 1) * QS_STR + q] = f2tf32(v.y);
        Qs[(c4 + 2) * QS_STR + q] = f2tf32(v.z);
        Qs[(c4 + 3) * QS_STR + q] = f2tf32(v.w);
    }

    float O[16][4];
#pragma unroll
    for (int nt = 0; nt < 16; nt++)
#pragma unroll
        for (int f = 0; f < 4; f++) O[nt][f] = 0.f;
    float m0 = neg_inf(), m1 = neg_inf(), l0 = 0.f, l1 = 0.f;

    const float* Kg = g_K + (size_t)kvh * KTOT * HEADD;
    const float* Vg = g_V + (size_t)kvh * KTOT * HEADD;
    const int q0 = qt0 + qw + r0;
    const int q1 = q0 + 8;

    int kmax = NSNW + qt0 + 64;
    if (kmax > KTOT) kmax = KTOT;

    for (int j0 = 0; j0 < kmax; j0 += 64) {
        __syncthreads();   // previous tile's consumers done
        // ---- load K/V tiles ----
        for (int i = tid; i < 64 * 32; i += 128) {
            int key = i >> 5, c4 = (i & 31) * 4;
            int j = j0 + key;
            float4 kv, vv;
            if (j < KTOT) {
                kv = *(const float4*)(Kg + (size_t)j * HEADD + c4);
                vv = *(const float4*)(Vg + (size_t)j * HEADD + c4);
            } else {
                kv = make_float4(0.f, 0.f, 0.f, 0.f);
                vv = kv;
            }
            Ks[(c4 + 0) * QS_STR + key] = f2tf32(kv.x);
            Ks[(c4 + 1) * QS_STR + key] = f2tf32(kv.y);
            Ks[(c4 + 2) * QS_STR + key] = f2tf32(kv.z);
            Ks[(c4 + 3) * QS_STR + key] = f2tf32(kv.w);
            uint4 u = {f2tf32(vv.x), f2tf32(vv.y), f2tf32(vv.z), f2tf32(vv.w)};
            *(uint4*)&Vs[key * VS_STR + c4] = u;
        }
        if (tid < 64) {
            int j = j0 + tid;
            biasS[tid] = (j < NSNW) ? g_bias[j] : 0.f;
        }
        __syncthreads();

        // ---- S = Q @ K^T  (16 x 64 per warp) ----
        float S[8][4];
#pragma unroll
        for (int nt = 0; nt < 8; nt++)
#pragma unroll
            for (int f = 0; f < 4; f++) S[nt][f] = 0.f;

#pragma unroll
        for (int kk = 0; kk < 16; kk++) {
            const int kb = kk * 8;
            uint32_t a0 = Qs[(kb + cq) * QS_STR + qw + r0];
            uint32_t a1 = Qs[(kb + cq) * QS_STR + qw + r0 + 8];
            uint32_t a2 = Qs[(kb + 4 + cq) * QS_STR + qw + r0];
            uint32_t a3 = Qs[(kb + 4 + cq) * QS_STR + qw + r0 + 8];
#pragma unroll
            for (int nt = 0; nt < 8; nt++) {
                uint32_t b0 = Ks[(kb + cq) * QS_STR + nt * 8 + r0];
                uint32_t b1 = Ks[(kb + 4 + cq) * QS_STR + nt * 8 + r0];
                mma_tf32(S[nt], a0, a1, a2, a3, b0, b1);
            }
        }

        // ---- softmax (online) ----
        float rm0 = neg_inf(), rm1 = neg_inf();
#pragma unroll
        for (int nt = 0; nt < 8; nt++) {
            int col = nt * 8 + cq * 2;
            int ja = j0 + col, jb = ja + 1;
            float ba = biasS[col], bb = biasS[col + 1];
            float s0 = (ja <= q0 + NSNW) ? S[nt][0] * ATTN_SCALE + ba : neg_inf();
            float s1 = (jb <= q0 + NSNW) ? S[nt][1] * ATTN_SCALE + bb : neg_inf();
            float s2 = (ja <= q1 + NSNW) ? S[nt][2] * ATTN_SCALE + ba : neg_inf();
            float s3 = (jb <= q1 + NSNW) ? S[nt][3] * ATTN_SCALE + bb : neg_inf();
            S[nt][0] = s0; S[nt][1] = s1; S[nt][2] = s2; S[nt][3] = s3;
            rm0 = fmaxf(rm0, fmaxf(s0, s1));
            rm1 = fmaxf(rm1, fmaxf(s2, s3));
        }
        rm0 = fmaxf(rm0, __shfl_xor_sync(0xffffffffu, rm0, 1));
        rm0 = fmaxf(rm0, __shfl_xor_sync(0xffffffffu, rm0, 2));
        rm1 = fmaxf(rm1, __shfl_xor_sync(0xffffffffu, rm1, 1));
        rm1 = fmaxf(rm1, __shfl_xor_sync(0xffffffffu, rm1, 2));

        float mn0 = fmaxf(m0, rm0);
        float mn1 = fmaxf(m1, rm1);
        float f0 = __expf(m0 - mn0);   // m=-inf, mn finite -> 0
        float f1 = __expf(m1 - mn1);
        m0 = mn0; m1 = mn1;
        l0 *= f0; l1 *= f1;
#pragma unroll
        for (int nt = 0; nt < 16; nt++) {
            O[nt][0] *= f0; O[nt][1] *= f0;
            O[nt][2] *= f1; O[nt][3] *= f1;
        }

        float ps0 = 0.f, ps1 = 0.f;
#pragma unroll
        for (int nt = 0; nt < 8; nt++) {
            int col = nt * 8 + cq * 2;
            float p0 = __expf(S[nt][0] - mn0);
            float p1 = __expf(S[nt][1] - mn0);
            float p2 = __expf(S[nt][2] - mn1);
            float p3 = __expf(S[nt][3] - mn1);
            ps0 += p0 + p1;
            ps1 += p2 + p3;
            Ps[(col + 0) * QS_STR + qw + r0]     = f2tf32(p0);
            Ps[(col + 1) * QS_STR + qw + r0]     = f2tf32(p1);
            Ps[(col + 0) * QS_STR + qw + r0 + 8] = f2tf32(p2);
            Ps[(col + 1) * QS_STR + qw + r0 + 8] = f2tf32(p3);
        }
        ps0 += __shfl_xor_sync(0xffffffffu, ps0, 1);
        ps0 += __shfl_xor_sync(0xffffffffu, ps0, 2);
        ps1 += __shfl_xor_sync(0xffffffffu, ps1, 1);
        ps1 += __shfl_xor_sync(0xffffffffu, ps1, 2);
        l0 += ps0; l1 += ps1;

        __syncwarp();

        // ---- O += P @ V ----
#pragma unroll
        for (int kk = 0; kk < 8; kk++) {
            const int kb = kk * 8;
            uint32_t a0 = Ps[(kb + cq) * QS_STR + qw + r0];
            uint32_t a1 = Ps[(kb + cq) * QS_STR + qw + r0 + 8];
            uint32_t a2 = Ps[(kb + 4 + cq) * QS_STR + qw + r0];
            uint32_t a3 = Ps[(kb + 4 + cq) * QS_STR + qw + r0 + 8];
#pragma unroll
            for (int nt = 0; nt < 16; nt++) {
                uint32_t b0 = Vs[(kb + cq) * VS_STR + nt * 8 + r0];
                uint32_t b1 = Vs[(kb + 4 + cq) * VS_STR + nt * 8 + r0];
                mma_tf32(O[nt], a0, a1, a2, a3, b0, b1);
            }
        }
    }

    // ---- normalize + write ----
    float inv0 = 1.f / l0, inv1 = 1.f / l1;
    float* og = g_attn + (size_t)0 * DMODEL + h * HEADD;
#pragma unroll
    for (int nt = 0; nt < 16; nt++) {
        int c = nt * 8 + cq * 2;
        float2 v0 = {O[nt][0] * inv0, O[nt][1] * inv0};
        float2 v1 = {O[nt][2] * inv1, O[nt][3] * inv1};
        *(float2*)(og + (size_t)q0 * DMODEL + c) = v0;
        *(float2*)(og + (size_t)q1 * DMODEL + c) = v1;
    }
}

// ---------------- launch ----------------
extern "C" void kernel_launch(void* const* d_in, const int* in_sizes, int n_in,
                              void* d_out, int out_size) {
    const float* hidden    = (const float*)d_in[0];
    const float* sink_k    = (const float*)d_in[1];
    const float* sink_v    = (const float*)d_in[2];
    const float* win_k     = (const float*)d_in[3];
    const float* win_v     = (const float*)d_in[4];
    const int*   sink_pos  = (const int*)d_in[5];
    const int*   key_pos   = (const int*)d_in[6];
    const float* sink_mask = (const float*)d_in[7];
    const float* key_mask  = (const float*)d_in[8];
    const float* Wq        = (const float*)d_in[9];
    const float* Wk        = (const float*)d_in[10];
    const float* Wv        = (const float*)d_in[11];
    const float* Wo        = (const float*)d_in[12];
    float*       out       = (float*)d_out;

    float *pq, *pk, *pv, *pattn;
    cudaGetSymbolAddress((void**)&pq, g_q);
    cudaGetSymbolAddress((void**)&pk, g_kproj);
    cudaGetSymbolAddress((void**)&pv, g_vproj);
    cudaGetSymbolAddress((void**)&pattn, g_attn);

    static bool attr_set = false;
    if (!attr_set) {
        cudaFuncSetAttribute(attn_mma_kernel,
                             cudaFuncAttributeMaxDynamicSharedMemorySize,
                             ATTN_SMEM_BYTES);
        attr_set = true;
    }

    maxpos_kernel<<<1, 256>>>(sink_pos, key_pos);
    bias_kernel<<<(NSNW + 255) / 256, 256>>>(sink_mask, key_mask);

    // projections (tensor cores, tf32)
    gemm_tf32<<<dim3(DMODEL / 128, QLEN / 128), 256>>>(hidden, Wq, pq, QLEN, DMODEL, DMODEL);
    gemm_tf32<<<dim3(KVDIM / 128, QLEN / 128), 256>>>(hidden, Wk, pk, QLEN, KVDIM, DMODEL);
    gemm_tf32<<<dim3(KVDIM / 128, QLEN / 128), 256>>>(hidden, Wv, pv, QLEN, KVDIM, DMODEL);

    // RoPE + cache assembly
    rope_q_kernel<<<(QLEN * NHEAD * 64 + 255) / 256, 256>>>();
    build_cache_kernel<<<(NKVH * KTOT * 64 + 255) / 256, 256>>>(
        sink_k, sink_v, win_k, win_v, sink_pos, key_pos);

    // attention (tensor cores, tf32 flash)
    attn_mma_kernel<<<dim3(NHEAD, QLEN / 64), 128, ATTN_SMEM_BYTES>>>();

    // output projection
    gemm_tf32<<<dim3(DMODEL / 128, QLEN / 128), 256>>>(pattn, Wo, out, QLEN, DMODEL, DMODEL);
}

// round 5
// speedup vs baseline: 5.8300x; 2.5796x over previous
#include <cuda_runtime.h>
#include <cuda_bf16.h>
#include <cstdint>

// ---------------- Problem constants ----------------
#define QLEN   2048
#define DMODEL 4096
#define NHEAD  32
#define NKVH   8
#define HEADD  128
#define NSINK  4
#define NWIN   2048
#define NSNW   (NSINK + NWIN)          // 2052
#define KTOT   (NSNW + QLEN)           // 4100
#define GRP    (NHEAD / NKVH)          // 4
#define KVDIM  (NKVH * HEADD)          // 1024

#define NEG_BIG (-3.4028234663852886e38f)   // finfo(float32).min
#define LOG10000_OVER_64 0.14391156831212787f
#define ATTN_SCALE 0.08838834764831845f     // 1/sqrt(128)

// ---------------- Scratch (device globals; no runtime alloc) ----------------
__device__ float g_q[QLEN * DMODEL];        // q proj -> RoPE'd, tf32-rounded
__device__ float g_kproj[QLEN * KVDIM];
__device__ float g_vproj[QLEN * KVDIM];
__device__ float g_K[NKVH * KTOT * HEADD];  // RoPE'd K cache, tf32-rounded
__device__ float g_V[NKVH * KTOT * HEADD];  // V cache, tf32-rounded
__device__ float g_attn[QLEN * DMODEL];     // attention output (pre-Wo)
__device__ float g_bias[NSNW];              // cache bias (mask * NEG)
__device__ int   g_maxpos;

__device__ __forceinline__ float neg_inf() { return __int_as_float(0xff800000u); }

__device__ __forceinline__ uint32_t f2tf32(float x) {
    uint32_t u;
    asm("cvt.rna.tf32.f32 %0, %1;" : "=r"(u) : "f"(x));
    return u;
}
__device__ __forceinline__ float f2tf32f(float x) {
    return __uint_as_float(f2tf32(x));
}

__device__ __forceinline__ void mma_tf32(float d[4],
                                         uint32_t a0, uint32_t a1, uint32_t a2, uint32_t a3,
                                         uint32_t b0, uint32_t b1) {
    asm volatile(
        "mma.sync.aligned.m16n8k8.row.col.f32.tf32.tf32.f32 "
        "{%0,%1,%2,%3}, {%4,%5,%6,%7}, {%8,%9}, {%0,%1,%2,%3};\n"
        : "+f"(d[0]), "+f"(d[1]), "+f"(d[2]), "+f"(d[3])
        : "r"(a0), "r"(a1), "r"(a2), "r"(a3), "r"(b0), "r"(b1));
}

__device__ __forceinline__ void cp16(uint32_t dst, const float* src, bool v) {
    asm volatile("cp.async.cg.shared.global [%0], [%1], 16, %2;\n"
                 :: "r"(dst), "l"(src), "r"(v ? 16 : 0) : "memory");
}
__device__ __forceinline__ void cp_commit() {
    asm volatile("cp.async.commit_group;\n" ::: "memory");
}
__device__ __forceinline__ void cp_wait0() {
    asm volatile("cp.async.wait_group 0;\n" ::: "memory");
}

// ---------------- max position + bias precompute ----------------
__global__ void maxpos_kernel(const int* __restrict__ sink_pos,
                              const int* __restrict__ key_pos) {
    __shared__ int sm[256];
    int tid = threadIdx.x;
    int v = -2147483647;
    for (int i = tid; i < NWIN; i += 256) v = max(v, key_pos[i]);
    for (int i = tid; i < NSINK; i += 256) v = max(v, sink_pos[i]);
    sm[tid] = v;
    __syncthreads();
    for (int s = 128; s > 0; s >>= 1) {
        if (tid < s) sm[tid] = max(sm[tid], sm[tid + s]);
        __syncthreads();
    }
    if (tid == 0) g_maxpos = sm[0] + 1;
}

__global__ void bias_kernel(const float* __restrict__ sink_mask,
                            const float* __restrict__ key_mask) {
    int i = blockIdx.x * blockDim.x + threadIdx.x;
    if (i >= NSNW) return;
    float m = (i < NSINK) ? sink_mask[i] : key_mask[i - NSINK];
    g_bias[i] = m * NEG_BIG;
}

// ---------------- TF32 tensor-core GEMM (unchanged layout; 2 CTAs/SM) ----------------
#define GSTR 136
__global__ void __launch_bounds__(256, 2) gemm_tf32(
    const float* __restrict__ A, const float* __restrict__ B,
    float* __restrict__ C, int M, int N, int K) {
    __shared__ uint32_t As[32][GSTR];   // As[k][m]
    __shared__ uint32_t Bs[32][GSTR];   // Bs[k][n]

    const int tid  = threadIdx.x;
    const int lane = tid & 31;
    const int warp = tid >> 5;
    const int wm   = (warp >> 1) * 32;
    const int wn   = (warp & 1) * 64;
    const int cRow = blockIdx.y * 128;
    const int cCol = blockIdx.x * 128;
    const int r0   = lane >> 2;
    const int cq   = lane & 3;

    float acc[2][8][4];
#pragma unroll
    for (int mt = 0; mt < 2; mt++)
#pragma unroll
        for (int nt = 0; nt < 8; nt++)
#pragma unroll
            for (int f = 0; f < 4; f++) acc[mt][nt][f] = 0.f;

    for (int k0 = 0; k0 < K; k0 += 32) {
#pragma unroll
        for (int i = 0; i < 4; i++) {          // A tile: 128 x 32
            int e = (i * 256 + tid) * 4;
            int r = e >> 5, c = e & 31;
            float4 v = *(const float4*)(A + (size_t)(cRow + r) * K + k0 + c);
            As[c + 0][r] = f2tf32(v.x);
            As[c + 1][r] = f2tf32(v.y);
            As[c + 2][r] = f2tf32(v.z);
            As[c + 3][r] = f2tf32(v.w);
        }
#pragma unroll
        for (int i = 0; i < 4; i++) {          // B tile: 32 x 128
            int e = (i * 256 + tid) * 4;
            int r = e >> 7, c = e & 127;
            float4 v = *(const float4*)(B + (size_t)(k0 + r) * N + cCol + c);
            uint4 u = {f2tf32(v.x), f2tf32(v.y), f2tf32(v.z), f2tf32(v.w)};
            *(uint4*)&Bs[r][c] = u;
        }
        __syncthreads();

#pragma unroll
        for (int kk = 0; kk < 4; kk++) {
            const int kb = kk * 8;
            uint32_t af[2][4];
#pragma unroll
            for (int mt = 0; mt < 2; mt++) {
                int mr = wm + mt * 16 + r0;
                af[mt][0] = As[kb + cq][mr];
                af[mt][1] = As[kb + cq][mr + 8];
                af[mt][2] = As[kb + 4 + cq][mr];
                af[mt][3] = As[kb + 4 + cq][mr + 8];
            }
#pragma unroll
            for (int nt = 0; nt < 8; nt++) {
                int nc = wn + nt * 8 + r0;
                uint32_t b0 = Bs[kb + cq][nc];
                uint32_t b1 = Bs[kb + 4 + cq][nc];
                mma_tf32(acc[0][nt], af[0][0], af[0][1], af[0][2], af[0][3], b0, b1);
                mma_tf32(acc[1][nt], af[1][0], af[1][1], af[1][2], af[1][3], b0, b1);
            }
        }
        __syncthreads();
    }

#pragma unroll
    for (int mt = 0; mt < 2; mt++)
#pragma unroll
        for (int nt = 0; nt < 8; nt++) {
            int r = cRow + wm + mt * 16 + r0;
            int c = cCol + wn + nt * 8 + cq * 2;
            float2 v0 = {acc[mt][nt][0], acc[mt][nt][1]};
            float2 v1 = {acc[mt][nt][2], acc[mt][nt][3]};
            *(float2*)(C + (size_t)r * N + c)       = v0;
            *(float2*)(C + (size_t)(r + 8) * N + c) = v1;
        }
}

// ---------------- RoPE on q (in place, writes tf32-rounded) ----------------
__global__ void rope_q_kernel() {
    int idx = blockIdx.x * blockDim.x + threadIdx.x;
    if (idx >= QLEN * NHEAD * 64) return;
    int i  = idx & 63;
    int hq = idx >> 6;
    int h  = hq & (NHEAD - 1);
    int t  = hq >> 5;
    float* p = g_q + (size_t)t * DMODEL + h * HEADD;
    float pos = (float)(g_maxpos + t);
    float freq = expf(-(float)i * LOG10000_OVER_64);
    float ang = pos * freq;
    float c, s;
    sincosf(ang, &s, &c);
    float x1 = p[i], x2 = p[i + 64];
    p[i]      = f2tf32f(x1 * c - x2 * s);
    p[i + 64] = f2tf32f(x2 * c + x1 * s);
}

// ---------------- Build concatenated K (RoPE'd) and V caches (tf32-rounded) ----------------
__global__ void build_cache_kernel(const float* __restrict__ sink_k,
                                   const float* __restrict__ sink_v,
                                   const float* __restrict__ win_k,
                                   const float* __restrict__ win_v,
                                   const int* __restrict__ sink_pos,
                                   const int* __restrict__ key_pos) {
    int idx = blockIdx.x * blockDim.x + threadIdx.x;
    if (idx >= NKVH * KTOT * 64) return;
    int i   = idx & 63;
    int rj  = idx >> 6;
    int j   = rj % KTOT;
    int kvh = rj / KTOT;

    const float* kp;
    const float* vp;
    int pos;
    if (j < NSINK) {
        kp = sink_k + (size_t)(kvh * NSINK + j) * HEADD;
        vp = sink_v + (size_t)(kvh * NSINK + j) * HEADD;
        pos = sink_pos[j];
    } else if (j < NSNW) {
        int w = j - NSINK;
        kp = win_k + (size_t)(kvh * NWIN + w) * HEADD;
        vp = win_v + (size_t)(kvh * NWIN + w) * HEADD;
        pos = key_pos[w];
    } else {
        int t = j - NSNW;
        kp = g_kproj + (size_t)t * KVDIM + kvh * HEADD;
        vp = g_vproj + (size_t)t * KVDIM + kvh * HEADD;
        pos = g_maxpos + t;
    }

    float freq = expf(-(float)i * LOG10000_OVER_64);
    float ang = (float)pos * freq;
    float c, s;
    sincosf(ang, &s, &c);
    float x1 = kp[i], x2 = kp[i + 64];

    size_t out = ((size_t)kvh * KTOT + j) * HEADD;
    g_K[out + i]      = f2tf32f(x1 * c - x2 * s);
    g_K[out + i + 64] = f2tf32f(x2 * c + x1 * s);
    g_V[out + i]      = f2tf32f(vp[i]);
    g_V[out + i + 64] = f2tf32f(vp[i + 64]);
}

// ---------------- Flash attention v3: 128q tile, 8 warps, reg-resident Q, cp.async ----------------
// Smem word layout (dynamic):
//   buf0: Ks0[64][132] @ 0       (8448 w)   Vs0[64][136] @ 8448  (8704 w)
//   buf1: Ks1[64][132] @ 17152              Vs1[64][136] @ 25600
//   (Qstage[128][132] overlaps buf region during prologue: 16896 w <= 34304 w)
//   Ps[128][68] @ 34304 (8704 w)
// total 43008 words = 172032 B
#define KS_STR 132
#define VS_STR 136
#define PS_STR 68
#define BUF_WORDS (64 * KS_STR + 64 * VS_STR)     // 17152
#define PS_OFF    (2 * BUF_WORDS)                  // 34304
#define ATTN_SMEM_BYTES ((PS_OFF + 128 * PS_STR) * 4)

__global__ void __launch_bounds__(256, 1) attn_mma_kernel() {
    extern __shared__ uint32_t smw[];
    const uint32_t smem_base = (uint32_t)__cvta_generic_to_shared(smw);

    const int h    = blockIdx.x;
    const int kvh  = h >> 2;                         // GRP = 4
    const int qt0  = (gridDim.y - 1 - blockIdx.y) * 128;  // long blocks first
    const int tid  = threadIdx.x;
    const int lane = tid & 31;
    const int warp = tid >> 5;
    const int qw   = warp * 16;
    const int r0   = lane >> 2;
    const int cq   = lane & 3;

    const float* Kg = g_K + (size_t)kvh * KTOT * HEADD;
    const float* Vg = g_V + (size_t)kvh * KTOT * HEADD;

    // ---- prologue: stage Q tile [128q][128d] into smem (rows padded to 132) ----
    {
        const float* qg = g_q + (size_t)qt0 * DMODEL + h * HEADD;
        for (int i = tid; i < 128 * 32; i += 256) {
            int q = i >> 5, c4 = (i & 31) * 4;
            uint4 v = *(const uint4*)(qg + (size_t)q * DMODEL + c4);
            *(uint4*)&smw[q * KS_STR + c4] = v;
        }
    }
    __syncthreads();

    // ---- extract Q fragments to registers: QA[16 kk][4] ----
    uint32_t QA[16][4];
#pragma unroll
    for (int kk = 0; kk < 16; kk++) {
        int kb = kk * 8;
        QA[kk][0] = smw[(qw + r0) * KS_STR + kb + cq];
        QA[kk][1] = smw[(qw + r0 + 8) * KS_STR + kb + cq];
        QA[kk][2] = smw[(qw + r0) * KS_STR + kb + cq + 4];
        QA[kk][3] = smw[(qw + r0 + 8) * KS_STR + kb + cq + 4];
    }
    __syncthreads();

    float O[16][4];
#pragma unroll
    for (int nt = 0; nt < 16; nt++)
#pragma unroll
        for (int f = 0; f < 4; f++) O[nt][f] = 0.f;
    float m0 = neg_inf(), m1 = neg_inf(), l0 = 0.f, l1 = 0.f;

    const int q0 = qt0 + qw + r0;
    const int q1 = q0 + 8;

    int kmax = NSNW + qt0 + 128;
    if (kmax > KTOT) kmax = KTOT;
    const int ntiles = (kmax + 63) >> 6;

    // ---- prefetch tile 0 into buf 0 ----
    {
        const int j0 = 0;
        uint32_t kbase = smem_base;
        uint32_t vbase = smem_base + 64 * KS_STR * 4;
        for (int i = tid; i < 2048; i += 256) {
            int key = i >> 5, c = i & 31;
            int j = j0 + key;
            bool v = (j < KTOT);
            int jc = v ? j : (KTOT - 1);
            cp16(kbase + (key * KS_STR + c * 4) * 4, Kg + (size_t)jc * HEADD + c * 4, v);
            cp16(vbase + (key * VS_STR + c * 4) * 4, Vg + (size_t)jc * HEADD + c * 4, v);
        }
        cp_commit();
    }

    for (int t = 0; t < ntiles; t++) {
        const int j0 = t * 64;
        const int buf = t & 1;
        const uint32_t* Ks = smw + buf * BUF_WORDS;
        const uint32_t* Vs = Ks + 64 * KS_STR;
        uint32_t* Ps = smw + PS_OFF;

        cp_wait0();
        __syncthreads();

        // prefetch next tile into other buffer
        if (t + 1 < ntiles) {
            const int jn = j0 + 64;
            uint32_t kbase = smem_base + (buf ^ 1) * BUF_WORDS * 4;
            uint32_t vbase = kbase + 64 * KS_STR * 4;
            for (int i = tid; i < 2048; i += 256) {
                int key = i >> 5, c = i & 31;
                int j = jn + key;
                bool v = (j < KTOT);
                int jc = v ? j : (KTOT - 1);
                cp16(kbase + (key * KS_STR + c * 4) * 4, Kg + (size_t)jc * HEADD + c * 4, v);
                cp16(vbase + (key * VS_STR + c * 4) * 4, Vg + (size_t)jc * HEADD + c * 4, v);
            }
            cp_commit();
        }

        // preload bias for this tile's columns
        float bb[8][2];
#pragma unroll
        for (int nt = 0; nt < 8; nt++) {
            int ja = j0 + nt * 8 + cq * 2;
            bb[nt][0] = (ja < NSNW) ? g_bias[ja] : 0.f;
            bb[nt][1] = (ja + 1 < NSNW) ? g_bias[ja + 1] : 0.f;
        }

        // ---- S = Q @ K^T  (16 x 64 per warp) ----
        float S[8][4];
#pragma unroll
        for (int nt = 0; nt < 8; nt++)
#pragma unroll
            for (int f = 0; f < 4; f++) S[nt][f] = 0.f;

#pragma unroll
        for (int kk = 0; kk < 16; kk++) {
            const int kb = kk * 8;
#pragma unroll
            for (int nt = 0; nt < 8; nt++) {
                uint32_t b0 = Ks[(nt * 8 + r0) * KS_STR + kb + cq];
                uint32_t b1 = Ks[(nt * 8 + r0) * KS_STR + kb + cq + 4];
                mma_tf32(S[nt], QA[kk][0], QA[kk][1], QA[kk][2], QA[kk][3], b0, b1);
            }
        }

        // ---- online softmax ----
        float rm0 = neg_inf(), rm1 = neg_inf();
#pragma unroll
        for (int nt = 0; nt < 8; nt++) {
            int ja = j0 + nt * 8 + cq * 2;
            int jb = ja + 1;
            float s0 = (ja <= q0 + NSNW) ? S[nt][0] * ATTN_SCALE + bb[nt][0] : neg_inf();
            float s1 = (jb <= q0 + NSNW) ? S[nt][1] * ATTN_SCALE + bb[nt][1] : neg_inf();
            float s2 = (ja <= q1 + NSNW) ? S[nt][2] * ATTN_SCALE + bb[nt][0] : neg_inf();
            float s3 = (jb <= q1 + NSNW) ? S[nt][3] * ATTN_SCALE + bb[nt][1] : neg_inf();
            S[nt][0] = s0; S[nt][1] = s1; S[nt][2] = s2; S[nt][3] = s3;
            rm0 = fmaxf(rm0, fmaxf(s0, s1));
            rm1 = fmaxf(rm1, fmaxf(s2, s3));
        }
        rm0 = fmaxf(rm0, __shfl_xor_sync(0xffffffffu, rm0, 1));
        rm0 = fmaxf(rm0, __shfl_xor_sync(0xffffffffu, rm0, 2));
        rm1 = fmaxf(rm1, __shfl_xor_sync(0xffffffffu, rm1, 1));
        rm1 = fmaxf(rm1, __shfl_xor_sync(0xffffffffu, rm1, 2));

        float mn0 = fmaxf(m0, rm0);
        float mn1 = fmaxf(m1, rm1);
        float mns0 = (mn0 == neg_inf()) ? 0.f : mn0;
        float mns1 = (mn1 == neg_inf()) ? 0.f : mn1;
        float f0 = __expf(m0 - mns0);   // m=-inf -> 0; both -inf -> l was 0
        float f1 = __expf(m1 - mns1);
        if (m0 == neg_inf()) f0 = 0.f;
        if (m1 == neg_inf()) f1 = 0.f;
        m0 = mn0; m1 = mn1;
        l0 *= f0; l1 *= f1;
#pragma unroll
        for (int nt = 0; nt < 16; nt++) {
            O[nt][0] *= f0; O[nt][1] *= f0;
            O[nt][2] *= f1; O[nt][3] *= f1;
        }

        float ps0 = 0.f, ps1 = 0.f;
#pragma unroll
        for (int nt = 0; nt < 8; nt++) {
            int col = nt * 8 + cq * 2;
            float p0 = __expf(S[nt][0] - mns0);
            float p1 = __expf(S[nt][1] - mns0);
            float p2 = __expf(S[nt][2] - mns1);
            float p3 = __expf(S[nt][3] - mns1);
            ps0 += p0 + p1;
            ps1 += p2 + p3;
            *(uint2*)&Ps[(qw + r0) * PS_STR + col]     = make_uint2(f2tf32(p0), f2tf32(p1));
            *(uint2*)&Ps[(qw + r0 + 8) * PS_STR + col] = make_uint2(f2tf32(p2), f2tf32(p3));
        }
        ps0 += __shfl_xor_sync(0xffffffffu, ps0, 1);
        ps0 += __shfl_xor_sync(0xffffffffu, ps0, 2);
        ps1 += __shfl_xor_sync(0xffffffffu, ps1, 1);
        ps1 += __shfl_xor_sync(0xffffffffu, ps1, 2);
        l0 += ps0; l1 += ps1;

        __syncwarp();

        // ---- O += P @ V ----
#pragma unroll
        for (int kk = 0; kk < 8; kk++) {
            const int kb = kk * 8;
            uint32_t a0 = Ps[(qw + r0) * PS_STR + kb + cq];
            uint32_t a1 = Ps[(qw + r0 + 8) * PS_STR + kb + cq];
            uint32_t a2 = Ps[(qw + r0) * PS_STR + kb + cq + 4];
            uint32_t a3 = Ps[(qw + r0 + 8) * PS_STR + kb + cq + 4];
#pragma unroll
            for (int nt = 0; nt < 16; nt++) {
                uint32_t b0 = Vs[(kb + cq) * VS_STR + nt * 8 + r0];
                uint32_t b1 = Vs[(kb + cq + 4) * VS_STR + nt * 8 + r0];
                mma_tf32(O[nt], a0, a1, a2, a3, b0, b1);
            }
        }
    }

    // ---- normalize + write ----
    float inv0 = 1.f / l0, inv1 = 1.f / l1;
    float* og = g_attn + (size_t)h * HEADD;
#pragma unroll
    for (int nt = 0; nt < 16; nt++) {
        int c = nt * 8 + cq * 2;
        float2 v0 = {O[nt][0] * inv0, O[nt][1] * inv0};
        float2 v1 = {O[nt][2] * inv1, O[nt][3] * inv1};
        *(float2*)(og + (size_t)q0 * DMODEL + c) = v0;
        *(float2*)(og + (size_t)q1 * DMODEL + c) = v1;
    }
}

// ---------------- launch ----------------
extern "C" void kernel_launch(void* const* d_in, const int* in_sizes, int n_in,
                              void* d_out, int out_size) {
    const float* hidden    = (const float*)d_in[0];
    const float* sink_k    = (const float*)d_in[1];
    const float* sink_v    = (const float*)d_in[2];
    const float* win_k     = (const float*)d_in[3];
    const float* win_v     = (const float*)d_in[4];
    const int*   sink_pos  = (const int*)d_in[5];
    const int*   key_pos   = (const int*)d_in[6];
    const float* sink_mask = (const float*)d_in[7];
    const float* key_mask  = (const float*)d_in[8];
    const float* Wq        = (const float*)d_in[9];
    const float* Wk        = (const float*)d_in[10];
    const float* Wv        = (const float*)d_in[11];
    const float* Wo        = (const float*)d_in[12];
    float*       out       = (float*)d_out;

    float *pq, *pk, *pv, *pattn;
    cudaGetSymbolAddress((void**)&pq, g_q);
    cudaGetSymbolAddress((void**)&pk, g_kproj);
    cudaGetSymbolAddress((void**)&pv, g_vproj);
    cudaGetSymbolAddress((void**)&pattn, g_attn);

    static bool attr_set = false;
    if (!attr_set) {
        cudaFuncSetAttribute(attn_mma_kernel,
                             cudaFuncAttributeMaxDynamicSharedMemorySize,
                             ATTN_SMEM_BYTES);
        attr_set = true;
    }

    maxpos_kernel<<<1, 256>>>(sink_pos, key_pos);
    bias_kernel<<<(NSNW + 255) / 256, 256>>>(sink_mask, key_mask);

    // projections (tensor cores, tf32)
    gemm_tf32<<<dim3(DMODEL / 128, QLEN / 128), 256>>>(hidden, Wq, pq, QLEN, DMODEL, DMODEL);
    gemm_tf32<<<dim3(KVDIM / 128, QLEN / 128), 256>>>(hidden, Wk, pk, QLEN, KVDIM, DMODEL);
    gemm_tf32<<<dim3(KVDIM / 128, QLEN / 128), 256>>>(hidden, Wv, pv, QLEN, KVDIM, DMODEL);

    // RoPE + cache assembly (tf32-rounded outputs)
    rope_q_kernel<<<(QLEN * NHEAD * 64 + 255) / 256, 256>>>();
    build_cache_kernel<<<(NKVH * KTOT * 64 + 255) / 256, 256>>>(
        sink_k, sink_v, win_k, win_v, sink_pos, key_pos);

    // attention (tf32 mma flash, 128q tiles, double-buffered cp.async)
    attn_mma_kernel<<<dim3(NHEAD, QLEN / 128), 256, ATTN_SMEM_BYTES>>>();

    // output projection
    gemm_tf32<<<dim3(DMODEL / 128, QLEN / 128), 256>>>(pattn, Wo, out, QLEN, DMODEL, DMODEL);
}